// round 3
// baseline (speedup 1.0000x reference)
#include <cuda_runtime.h>
#include <math.h>

#define NREAL 12288
#define DIM   256
#define BM    128
#define BN    128
#define BK    8
#define TM    8
#define TN    8

// Scratch (no allocations allowed in kernel_launch)
__device__ float g_r2[NREAL];
__device__ float g_g2[NREAL];
__device__ unsigned int        g_real_min[NREAL];   // min sq-dist (float bits) per real column
__device__ unsigned long long  g_gen_min[NREAL];    // packed (sq bits << 32) | argmin index

__global__ void init_kernel() {
    int j = blockIdx.x * blockDim.x + threadIdx.x;
    if (j < NREAL) {
        g_real_min[j] = 0x7F800000u;                       // +inf
        g_gen_min[j]  = 0x7F800000FFFFFFFFULL;             // +inf, idx=max
    }
}

__global__ void norms_kernel(const float* __restrict__ real,
                             const float* __restrict__ gen) {
    __shared__ float red[256];
    int row = blockIdx.x;
    const float* src = (row < NREAL) ? real : gen;
    int r = (row < NREAL) ? row : row - NREAL;
    float v = src[(size_t)r * DIM + threadIdx.x];
    red[threadIdx.x] = v * v;
    __syncthreads();
    for (int o = 128; o > 0; o >>= 1) {
        if (threadIdx.x < o) red[threadIdx.x] += red[threadIdx.x + o];
        __syncthreads();
    }
    if (threadIdx.x == 0) {
        if (row < NREAL) g_r2[r] = red[0];
        else             g_g2[r] = red[0];
    }
}

// Fused distance-GEMM + column-min.  A = real (i dim), B = real or gen (j dim).
// sq(i,j) = r2[i] + b2[j] - 2*dot(a_i, b_j); column-min over i (diag excluded for real).
template<bool GEN>
__global__ __launch_bounds__(256, 2)
void dist_kernel(const float* __restrict__ A, const float* __restrict__ B) {
    __shared__ float As[BK][BM + 4];
    __shared__ float Bs[BK][BN + 4];
    __shared__ unsigned long long red[16][BN];   // also reused as float[16][BN] for !GEN

    const int tid = threadIdx.x;
    const int tx = tid & 15;
    const int ty = tid >> 4;
    const int i0 = blockIdx.y * BM;
    const int j0 = blockIdx.x * BN;

    float acc[TM][TN];
#pragma unroll
    for (int m = 0; m < TM; m++)
#pragma unroll
        for (int n = 0; n < TN; n++) acc[m][n] = 0.0f;

    const int lr = tid >> 1;          // 0..127: row within tile
    const int lk = (tid & 1) << 2;    // 0 or 4: k offset (float4)
    const float* Aptr = A + (size_t)(i0 + lr) * DIM + lk;
    const float* Bptr = B + (size_t)(j0 + lr) * DIM + lk;

    for (int k0 = 0; k0 < DIM; k0 += BK) {
        float4 a4 = *(const float4*)(Aptr + k0);
        float4 b4 = *(const float4*)(Bptr + k0);
        As[lk + 0][lr] = a4.x; As[lk + 1][lr] = a4.y;
        As[lk + 2][lr] = a4.z; As[lk + 3][lr] = a4.w;
        Bs[lk + 0][lr] = b4.x; Bs[lk + 1][lr] = b4.y;
        Bs[lk + 2][lr] = b4.z; Bs[lk + 3][lr] = b4.w;
        __syncthreads();
#pragma unroll
        for (int k = 0; k < BK; k++) {
            float a[TM], b[TN];
#pragma unroll
            for (int m = 0; m < TM; m++) a[m] = As[k][ty * TM + m];
#pragma unroll
            for (int n = 0; n < TN; n++) b[n] = Bs[k][tx * TN + n];
#pragma unroll
            for (int m = 0; m < TM; m++)
#pragma unroll
                for (int n = 0; n < TN; n++)
                    acc[m][n] = fmaf(a[m], b[n], acc[m][n]);
        }
        __syncthreads();
    }

    // Epilogue: squared distances + per-thread column mins
    float r2i[TM];
#pragma unroll
    for (int m = 0; m < TM; m++) r2i[m] = g_r2[i0 + ty * TM + m];

#pragma unroll
    for (int n = 0; n < TN; n++) {
        const int j = j0 + tx * TN + n;
        const float b2 = GEN ? g_g2[j] : g_r2[j];
        float best = __int_as_float(0x7f800000);
        int bidx = 0;
#pragma unroll
        for (int m = 0; m < TM; m++) {
            const int i = i0 + ty * TM + m;
            float sq = fmaxf(r2i[m] + b2 - 2.0f * acc[m][n], 0.0f);
            if (GEN) {
                if (sq < best) { best = sq; bidx = i; }   // ascending i: lowest idx on tie
            } else {
                if (i != j) best = fminf(best, sq);        // diagonal excluded
            }
        }
        if (GEN) {
            red[ty][tx * TN + n] =
                ((unsigned long long)__float_as_uint(best) << 32) | (unsigned)bidx;
        } else {
            ((float*)red)[ty * BN + tx * TN + n] = best;
        }
    }
    __syncthreads();

    if (tid < BN) {
        if (GEN) {
            unsigned long long p = red[0][tid];
#pragma unroll
            for (int t = 1; t < 16; t++) {
                unsigned long long q = red[t][tid];
                if (q < p) p = q;
            }
            atomicMin(&g_gen_min[j0 + tid], p);
        } else {
            const float* fr = (const float*)red;
            float p = fr[tid];
#pragma unroll
            for (int t = 1; t < 16; t++) p = fminf(p, fr[t * BN + tid]);
            atomicMin(&g_real_min[j0 + tid], __float_as_uint(p));
        }
    }
}

__global__ void final_kernel(float* __restrict__ out) {
    __shared__ float red[256];
    float s = 0.0f;
    for (int j = threadIdx.x; j < NREAL; j += 256) {
        unsigned long long p = g_gen_min[j];
        float d1 = sqrtf(__uint_as_float((unsigned)(p >> 32)));
        unsigned idx = (unsigned)(p & 0xFFFFFFFFu);
        float d2 = sqrtf(__uint_as_float(g_real_min[idx]));
        s += 1.0f / (1.0f + expf(-(d2 - d1) * 10.0f));   // sigmoid((d2-d1)/0.1)
    }
    red[threadIdx.x] = s;
    __syncthreads();
    for (int o = 128; o > 0; o >>= 1) {
        if (threadIdx.x < o) red[threadIdx.x] += red[threadIdx.x + o];
        __syncthreads();
    }
    if (threadIdx.x == 0) out[0] = -100.0f * red[0] / (float)NREAL;
}

extern "C" void kernel_launch(void* const* d_in, const int* in_sizes, int n_in,
                              void* d_out, int out_size) {
    const float* real = (const float*)d_in[0];
    const float* gen  = (const float*)d_in[1];
    float* out = (float*)d_out;

    init_kernel<<<(NREAL + 255) / 256, 256>>>();
    norms_kernel<<<2 * NREAL, 256>>>(real, gen);

    dim3 grid(NREAL / BN, NREAL / BM);
    dist_kernel<false><<<grid, 256>>>(real, real);
    dist_kernel<true ><<<grid, 256>>>(real, gen);

    final_kernel<<<1, 256>>>(out);
}

// round 8
// speedup vs baseline: 3.2967x; 3.2967x over previous
#include <cuda_runtime.h>
#include <math.h>
#include <stdint.h>

#define NREAL 12288
#define DIM   256
#define BM    128          // j rows per CTA
#define BN    256          // i cols per CTA
#define BK    32           // K floats per stage
#define NSTG  (DIM / BK)   // 8
#define NTHR  256
#define A_BYTES     (BM * BK * 4)            // 16384
#define STAGE_BYTES ((BM + BN) * BK * 4)     // 49152
#define SMEM_TOTAL  (3 * STAGE_BYTES)        // 147456

__device__ float g_r2[NREAL];
__device__ float g_g2[NREAL];
__device__ unsigned int       g_real_min[NREAL];
__device__ unsigned long long g_gen_min[NREAL];

// ---------------- helpers ----------------
static __device__ __forceinline__ uint32_t smem_u32(const void* p) {
    uint32_t a;
    asm("{ .reg .u64 t; cvta.to.shared.u64 t, %1; cvt.u32.u64 %0, t; }"
        : "=r"(a) : "l"(p));
    return a;
}

static __device__ __forceinline__ void cp16(uint32_t dst, const void* src) {
    asm volatile("cp.async.cg.shared.global [%0], [%1], 16;" :: "r"(dst), "l"(src));
}
#define CP_COMMIT() asm volatile("cp.async.commit_group;" ::: "memory")

static __device__ __forceinline__ uint32_t lds_tf32(uint32_t a) {
    float v; uint32_t o;
    asm("ld.shared.f32 %0, [%1];" : "=f"(v) : "r"(a));
    asm("cvt.rna.tf32.f32 %0, %1;" : "=r"(o) : "f"(v));
    return o;
}

static __device__ __forceinline__ void mma_tf32(
    float* d, const uint32_t* a, const uint32_t* b)
{
    asm volatile(
        "mma.sync.aligned.m16n8k8.row.col.f32.tf32.tf32.f32 "
        "{%0,%1,%2,%3}, {%4,%5,%6,%7}, {%8,%9}, {%0,%1,%2,%3};"
        : "+f"(d[0]), "+f"(d[1]), "+f"(d[2]), "+f"(d[3])
        : "r"(a[0]), "r"(a[1]), "r"(a[2]), "r"(a[3]), "r"(b[0]), "r"(b[1]));
}

// ---------------- small kernels ----------------
__global__ void init_kernel() {
    int j = blockIdx.x * blockDim.x + threadIdx.x;
    if (j < NREAL) {
        g_real_min[j] = 0x7F800000u;
        g_gen_min[j]  = 0x7F800000FFFFFFFFULL;
    }
}

__global__ void norms_kernel(const float* __restrict__ real,
                             const float* __restrict__ gen) {
    __shared__ float red[256];
    int row = blockIdx.x;
    const float* src = (row < NREAL) ? real : gen;
    int r = (row < NREAL) ? row : row - NREAL;
    float v = src[(size_t)r * DIM + threadIdx.x];
    red[threadIdx.x] = v * v;
    __syncthreads();
    for (int o = 128; o > 0; o >>= 1) {
        if (threadIdx.x < o) red[threadIdx.x] += red[threadIdx.x + o];
        __syncthreads();
    }
    if (threadIdx.x == 0) {
        if (row < NREAL) g_r2[r] = red[0];
        else             g_g2[r] = red[0];
    }
}

// ---------------- fused tf32 mma.sync distance + column-min ----------------
// m axis (rows of D) = j (gen rows for GEN, real rows for !GEN)
// n axis (cols of D) = i (real rows, the minimized dimension)
template<bool GEN>
__global__ __launch_bounds__(NTHR, 1)
void dist_mma_kernel(const float* __restrict__ Aj, const float* __restrict__ Br) {
    extern __shared__ __align__(1024) char dsm[];
    const uint32_t sbase = smem_u32(dsm);

    const int tid  = threadIdx.x;
    const int w    = tid >> 5, lane = tid & 31;
    const int g    = lane >> 2, s = lane & 3;
    const int wm   = w >> 2;          // 0..1
    const int wn   = w & 3;           // 0..3
    const int j0   = blockIdx.y * BM;
    const int i0   = blockIdx.x * BN;

    float d[4][8][4];
#pragma unroll
    for (int mt = 0; mt < 4; mt++)
#pragma unroll
        for (int nt = 0; nt < 8; nt++)
#pragma unroll
            for (int q = 0; q < 4; q++) d[mt][nt][q] = 0.0f;

    // per-thread fragment row byte offsets (within a stage's A / B region)
    uint32_t arow[4][2], brow[8];
#pragma unroll
    for (int mt = 0; mt < 4; mt++) {
        const int r = wm * 64 + mt * 16 + g;
        arow[mt][0] = (uint32_t)(r * 128);
        arow[mt][1] = (uint32_t)((r + 8) * 128);
    }
#pragma unroll
    for (int nt = 0; nt < 8; nt++)
        brow[nt] = (uint32_t)((wn * 64 + nt * 8 + g) * 128);

    // stage loader
    auto load_stage = [&](int st, int buf) {
        const int k0 = st * BK;
        const uint32_t ab = sbase + buf * STAGE_BYTES;
        const uint32_t bb = ab + A_BYTES;
#pragma unroll
        for (int t = 0; t < 4; t++) {
            const int l = tid + t * NTHR;         // 0..1023
            const int row = l >> 3, c = l & 7;
            cp16(ab + row * 128 + ((c ^ (row & 7)) << 4),
                 Aj + (size_t)(j0 + row) * DIM + k0 + c * 4);
        }
#pragma unroll
        for (int t = 0; t < 8; t++) {
            const int l = tid + t * NTHR;         // 0..2047
            const int row = l >> 3, c = l & 7;
            cp16(bb + row * 128 + ((c ^ (row & 7)) << 4),
                 Br + (size_t)(i0 + row) * DIM + k0 + c * 4);
        }
        CP_COMMIT();
    };

    load_stage(0, 0);
    load_stage(1, 1);

    for (int st = 0; st < NSTG; st++) {
        if (st < NSTG - 1) asm volatile("cp.async.wait_group 1;" ::: "memory");
        else               asm volatile("cp.async.wait_group 0;" ::: "memory");
        __syncthreads();
        if (st + 2 < NSTG) load_stage(st + 2, (st + 2) % 3);

        const uint32_t ab = sbase + (st % 3) * STAGE_BYTES;
        const uint32_t bb = ab + A_BYTES;
#pragma unroll
        for (int k8 = 0; k8 < 4; k8++) {
            const uint32_t c0 = (uint32_t)((2 * k8) ^ g);
            const uint32_t t0 = c0 * 16 + s * 4;
            const uint32_t t1 = (c0 ^ 1u) * 16 + s * 4;
            uint32_t afr[4][4], bfr[8][2];
#pragma unroll
            for (int mt = 0; mt < 4; mt++) {
                afr[mt][0] = lds_tf32(ab + arow[mt][0] + t0);
                afr[mt][1] = lds_tf32(ab + arow[mt][1] + t0);
                afr[mt][2] = lds_tf32(ab + arow[mt][0] + t1);
                afr[mt][3] = lds_tf32(ab + arow[mt][1] + t1);
            }
#pragma unroll
            for (int nt = 0; nt < 8; nt++) {
                bfr[nt][0] = lds_tf32(bb + brow[nt] + t0);
                bfr[nt][1] = lds_tf32(bb + brow[nt] + t1);
            }
#pragma unroll
            for (int mt = 0; mt < 4; mt++)
#pragma unroll
                for (int nt = 0; nt < 8; nt++)
                    mma_tf32(d[mt][nt], afr[mt], bfr[nt]);
        }
        __syncthreads();
    }

    // ---------------- epilogue: fused sq-dist + min over i ----------------
    float ri2[16];
    int   ii[16];
#pragma unroll
    for (int nt = 0; nt < 8; nt++)
#pragma unroll
        for (int c = 0; c < 2; c++) {
            const int i = i0 + wn * 64 + nt * 8 + 2 * s + c;
            ii[nt * 2 + c]  = i;
            ri2[nt * 2 + c] = g_r2[i];
        }

#pragma unroll
    for (int mt = 0; mt < 4; mt++) {
#pragma unroll
        for (int dl = 0; dl < 2; dl++) {
            const int j = j0 + wm * 64 + mt * 16 + g + dl * 8;
            const float jj2 = GEN ? g_g2[j] : g_r2[j];
            if (GEN) {
                unsigned long long best = 0x7F800000FFFFFFFFULL;
#pragma unroll
                for (int nt = 0; nt < 8; nt++)
#pragma unroll
                    for (int c = 0; c < 2; c++) {
                        const float sq = fmaxf(
                            ri2[nt * 2 + c] + jj2 - 2.0f * d[mt][nt][dl * 2 + c], 0.0f);
                        const unsigned long long pk =
                            ((unsigned long long)__float_as_uint(sq) << 32) |
                            (unsigned)ii[nt * 2 + c];
                        if (pk < best) best = pk;
                    }
                // reduce across the 4 lanes of the column group (lanes differ in s)
#pragma unroll
                for (int m = 1; m < 4; m <<= 1) {
                    unsigned long long o = __shfl_xor_sync(0xFFFFFFFFu, best, m);
                    if (o < best) best = o;
                }
                if (s == 0) atomicMin(&g_gen_min[j], best);
            } else {
                float best = __int_as_float(0x7f800000);
#pragma unroll
                for (int nt = 0; nt < 8; nt++)
#pragma unroll
                    for (int c = 0; c < 2; c++) {
                        const int i = ii[nt * 2 + c];
                        float sq = fmaxf(
                            ri2[nt * 2 + c] + jj2 - 2.0f * d[mt][nt][dl * 2 + c], 0.0f);
                        if (i != j) best = fminf(best, sq);
                    }
#pragma unroll
                for (int m = 1; m < 4; m <<= 1)
                    best = fminf(best, __shfl_xor_sync(0xFFFFFFFFu, best, m));
                if (s == 0) atomicMin(&g_real_min[j], __float_as_uint(best));
            }
        }
    }
}

__global__ void final_kernel(float* __restrict__ out) {
    __shared__ float red[256];
    float sacc = 0.0f;
    for (int j = threadIdx.x; j < NREAL; j += 256) {
        unsigned long long p = g_gen_min[j];
        float d1 = sqrtf(__uint_as_float((unsigned)(p >> 32)));
        unsigned idx = (unsigned)(p & 0xFFFFFFFFu);
        float d2 = sqrtf(__uint_as_float(g_real_min[idx]));
        sacc += 1.0f / (1.0f + expf(-(d2 - d1) * 10.0f));
    }
    red[threadIdx.x] = sacc;
    __syncthreads();
    for (int o = 128; o > 0; o >>= 1) {
        if (threadIdx.x < o) red[threadIdx.x] += red[threadIdx.x + o];
        __syncthreads();
    }
    if (threadIdx.x == 0) out[0] = -100.0f * red[0] / (float)NREAL;
}

// ---------------- launcher ----------------
extern "C" void kernel_launch(void* const* d_in, const int* in_sizes, int n_in,
                              void* d_out, int out_size) {
    const float* real = (const float*)d_in[0];
    const float* gen  = (const float*)d_in[1];
    float* out = (float*)d_out;

    cudaFuncSetAttribute(dist_mma_kernel<false>,
                         cudaFuncAttributeMaxDynamicSharedMemorySize, SMEM_TOTAL);
    cudaFuncSetAttribute(dist_mma_kernel<true>,
                         cudaFuncAttributeMaxDynamicSharedMemorySize, SMEM_TOTAL);

    init_kernel<<<(NREAL + 255) / 256, 256>>>();
    norms_kernel<<<2 * NREAL, 256>>>(real, gen);

    dim3 grid(NREAL / BN, NREAL / BM);   // 48 x 96
    dist_mma_kernel<false><<<grid, NTHR, SMEM_TOTAL>>>(real, real);
    dist_mma_kernel<true ><<<grid, NTHR, SMEM_TOTAL>>>(gen,  real);

    final_kernel<<<1, 256>>>(out);
}

// round 10
// speedup vs baseline: 4.2162x; 1.2789x over previous
#include <cuda_runtime.h>
#include <math.h>
#include <stdint.h>

#define NREAL 12288
#define DIM   256
#define BM    128          // j rows per CTA
#define BN    128          // i cols per CTA
#define BK    32           // K floats per stage
#define NSTG  (DIM / BK)   // 8
#define NTHR  256
#define NJB   (NREAL / BM)                   // 96
#define NIB   (NREAL / BN)                   // 96
#define NTRI  (NJB * (NJB + 1) / 2)          // 4656
#define A_BYTES     (BM * BK * 4)            // 16384
#define STAGE_BYTES ((BM + BN) * BK * 4)     // 32768
#define SMEM_TOTAL  (3 * STAGE_BYTES)        // 98304

__device__ float g_r2[NREAL];
__device__ float g_g2[NREAL];
__device__ unsigned int       g_real_min[NREAL];
__device__ unsigned long long g_gen_min[NREAL];

// ---------------- helpers ----------------
static __device__ __forceinline__ uint32_t smem_u32(const void* p) {
    uint32_t a;
    asm("{ .reg .u64 t; cvta.to.shared.u64 t, %1; cvt.u32.u64 %0, t; }"
        : "=r"(a) : "l"(p));
    return a;
}

static __device__ __forceinline__ void cp16(uint32_t dst, const void* src) {
    asm volatile("cp.async.cg.shared.global [%0], [%1], 16;" :: "r"(dst), "l"(src));
}
#define CP_COMMIT() asm volatile("cp.async.commit_group;" ::: "memory")

static __device__ __forceinline__ uint32_t lds_tf32(uint32_t a) {
    float v; uint32_t o;
    asm("ld.shared.f32 %0, [%1];" : "=f"(v) : "r"(a));
    asm("cvt.rna.tf32.f32 %0, %1;" : "=r"(o) : "f"(v));
    return o;
}

static __device__ __forceinline__ void mma_tf32(
    float* d, const uint32_t* a, const uint32_t* b)
{
    asm volatile(
        "mma.sync.aligned.m16n8k8.row.col.f32.tf32.tf32.f32 "
        "{%0,%1,%2,%3}, {%4,%5,%6,%7}, {%8,%9}, {%0,%1,%2,%3};"
        : "+f"(d[0]), "+f"(d[1]), "+f"(d[2]), "+f"(d[3])
        : "r"(a[0]), "r"(a[1]), "r"(a[2]), "r"(a[3]), "r"(b[0]), "r"(b[1]));
}

// ---------------- small kernels ----------------
__global__ void init_kernel() {
    int j = blockIdx.x * blockDim.x + threadIdx.x;
    if (j < NREAL) {
        g_real_min[j] = 0x7F800000u;
        g_gen_min[j]  = 0x7F800000FFFFFFFFULL;
    }
}

__global__ void norms_kernel(const float* __restrict__ real,
                             const float* __restrict__ gen) {
    __shared__ float red[256];
    int row = blockIdx.x;
    const float* src = (row < NREAL) ? real : gen;
    int r = (row < NREAL) ? row : row - NREAL;
    float v = src[(size_t)r * DIM + threadIdx.x];
    red[threadIdx.x] = v * v;
    __syncthreads();
    for (int o = 128; o > 0; o >>= 1) {
        if (threadIdx.x < o) red[threadIdx.x] += red[threadIdx.x + o];
        __syncthreads();
    }
    if (threadIdx.x == 0) {
        if (row < NREAL) g_r2[r] = red[0];
        else             g_g2[r] = red[0];
    }
}

// ---------------- fused tf32 mma.sync distance + mins ----------------
// m axis = j rows (gen rows for GEN, real rows for !GEN)
// n axis = i cols (real rows)
// GEN:  grid (NIB, NJB); min+argmin over i per j.
// !GEN: 1D grid over upper triangle (ib >= jb); symmetric — updates BOTH
//       row-mins (per j, over i) and col-mins (per i, over j).
template<bool GEN>
__global__ __launch_bounds__(NTHR, 2)
void dist_mma_kernel(const float* __restrict__ Aj, const float* __restrict__ Br) {
    extern __shared__ __align__(1024) char dsm[];
    const uint32_t sbase = smem_u32(dsm);

    int jb, ib;
    if (GEN) {
        jb = blockIdx.y; ib = blockIdx.x;
    } else {
        const int t = blockIdx.x;
        // cum(jb) = jb*96 - jb*(jb-1)/2 ; decode then fix up
        int p = (int)((193.0 - sqrt(193.0 * 193.0 - 8.0 * (double)t)) * 0.5);
        if (p < 0) p = 0;
        if (p > NJB - 1) p = NJB - 1;
        while (p + 1 <= NJB - 1 && ((p + 1) * NJB - ((p + 1) * p) / 2) <= t) p++;
        while (p > 0 && (p * NJB - (p * (p - 1)) / 2) > t) p--;
        jb = p;
        ib = jb + (t - (p * NJB - (p * (p - 1)) / 2));
    }
    const int j0 = jb * BM;
    const int i0 = ib * BN;

    const int tid  = threadIdx.x;
    const int w    = tid >> 5, lane = tid & 31;
    const int g    = lane >> 2, s = lane & 3;
    const int wm   = w >> 2;          // 0..1 (64 j-rows each)
    const int wn   = w & 3;           // 0..3 (32 i-cols each)

    float d[4][4][4];
#pragma unroll
    for (int mt = 0; mt < 4; mt++)
#pragma unroll
        for (int nt = 0; nt < 4; nt++)
#pragma unroll
            for (int q = 0; q < 4; q++) d[mt][nt][q] = 0.0f;

    uint32_t arow[4], brow[4];
#pragma unroll
    for (int mt = 0; mt < 4; mt++)
        arow[mt] = (uint32_t)((wm * 64 + mt * 16 + g) * 128);
#pragma unroll
    for (int nt = 0; nt < 4; nt++)
        brow[nt] = (uint32_t)((wn * 32 + nt * 8 + g) * 128);

    auto load_stage = [&](int st, int buf) {
        const int k0 = st * BK;
        const uint32_t ab = sbase + buf * STAGE_BYTES;
        const uint32_t bb = ab + A_BYTES;
#pragma unroll
        for (int t = 0; t < 4; t++) {
            const int l = tid + t * NTHR;      // 0..1023
            const int row = l >> 3, c = l & 7;
            cp16(ab + row * 128 + ((c ^ (row & 7)) << 4),
                 Aj + (size_t)(j0 + row) * DIM + k0 + c * 4);
        }
#pragma unroll
        for (int t = 0; t < 4; t++) {
            const int l = tid + t * NTHR;
            const int row = l >> 3, c = l & 7;
            cp16(bb + row * 128 + ((c ^ (row & 7)) << 4),
                 Br + (size_t)(i0 + row) * DIM + k0 + c * 4);
        }
        CP_COMMIT();
    };

    load_stage(0, 0);
    load_stage(1, 1);

    for (int st = 0; st < NSTG; st++) {
        if (st < NSTG - 1) asm volatile("cp.async.wait_group 1;" ::: "memory");
        else               asm volatile("cp.async.wait_group 0;" ::: "memory");
        __syncthreads();
        if (st + 2 < NSTG) load_stage(st + 2, (st + 2) % 3);

        const uint32_t ab = sbase + (st % 3) * STAGE_BYTES;
        const uint32_t bb = ab + A_BYTES;
#pragma unroll
        for (int k8 = 0; k8 < 4; k8++) {
            const uint32_t t0 = ((uint32_t)((2 * k8) ^ g)) * 16 + s * 4;
            const uint32_t t1 = ((uint32_t)((2 * k8 + 1) ^ g)) * 16 + s * 4;
            uint32_t afr[4][4], bfr[4][2];
#pragma unroll
            for (int mt = 0; mt < 4; mt++) {
                afr[mt][0] = lds_tf32(ab + arow[mt] + t0);
                afr[mt][1] = lds_tf32(ab + arow[mt] + 8 * 128 + t0);
                afr[mt][2] = lds_tf32(ab + arow[mt] + t1);
                afr[mt][3] = lds_tf32(ab + arow[mt] + 8 * 128 + t1);
            }
#pragma unroll
            for (int nt = 0; nt < 4; nt++) {
                bfr[nt][0] = lds_tf32(bb + brow[nt] + t0);
                bfr[nt][1] = lds_tf32(bb + brow[nt] + t1);
            }
#pragma unroll
            for (int mt = 0; mt < 4; mt++)
#pragma unroll
                for (int nt = 0; nt < 4; nt++)
                    mma_tf32(d[mt][nt], afr[mt], bfr[nt]);
        }
        __syncthreads();
    }

    // ------- epilogue: convert accumulators in place to squared distances -------
    float ri2[8];
#pragma unroll
    for (int nt = 0; nt < 4; nt++)
#pragma unroll
        for (int c = 0; c < 2; c++)
            ri2[nt * 2 + c] = g_r2[i0 + wn * 32 + nt * 8 + 2 * s + c];

    float rj2[8];
#pragma unroll
    for (int mt = 0; mt < 4; mt++)
#pragma unroll
        for (int dl = 0; dl < 2; dl++) {
            const int j = j0 + wm * 64 + mt * 16 + g + dl * 8;
            rj2[mt * 2 + dl] = GEN ? g_g2[j] : g_r2[j];
        }

#pragma unroll
    for (int mt = 0; mt < 4; mt++)
#pragma unroll
        for (int nt = 0; nt < 4; nt++)
#pragma unroll
            for (int dl = 0; dl < 2; dl++)
#pragma unroll
                for (int c = 0; c < 2; c++) {
                    float sq = fmaxf(ri2[nt * 2 + c] + rj2[mt * 2 + dl]
                                     - 2.0f * d[mt][nt][dl * 2 + c], 0.0f);
                    if (!GEN) {
                        const int i = i0 + wn * 32 + nt * 8 + 2 * s + c;
                        const int j = j0 + wm * 64 + mt * 16 + g + dl * 8;
                        if (i == j) sq = __int_as_float(0x7f800000);
                    }
                    d[mt][nt][dl * 2 + c] = sq;
                }

    if (GEN) {
        // min+argmin over i per j row; pack (sq_bits<<32)|i, lowest i on ties
#pragma unroll
        for (int mt = 0; mt < 4; mt++)
#pragma unroll
            for (int dl = 0; dl < 2; dl++) {
                const int j = j0 + wm * 64 + mt * 16 + g + dl * 8;
                unsigned long long best = 0x7F800000FFFFFFFFULL;
#pragma unroll
                for (int nt = 0; nt < 4; nt++)
#pragma unroll
                    for (int c = 0; c < 2; c++) {
                        const int i = i0 + wn * 32 + nt * 8 + 2 * s + c;
                        const unsigned long long pk =
                            ((unsigned long long)__float_as_uint(d[mt][nt][dl * 2 + c]) << 32)
                            | (unsigned)i;
                        if (pk < best) best = pk;
                    }
#pragma unroll
                for (int m = 1; m < 4; m <<= 1) {
                    unsigned long long o = __shfl_xor_sync(0xFFFFFFFFu, best, m);
                    if (o < best) best = o;
                }
                if (s == 0) atomicMin(&g_gen_min[j], best);
            }
    } else {
        // row direction: min over i per j
#pragma unroll
        for (int mt = 0; mt < 4; mt++)
#pragma unroll
            for (int dl = 0; dl < 2; dl++) {
                const int j = j0 + wm * 64 + mt * 16 + g + dl * 8;
                float best = __int_as_float(0x7f800000);
#pragma unroll
                for (int nt = 0; nt < 4; nt++)
#pragma unroll
                    for (int c = 0; c < 2; c++)
                        best = fminf(best, d[mt][nt][dl * 2 + c]);
#pragma unroll
                for (int m = 1; m < 4; m <<= 1)
                    best = fminf(best, __shfl_xor_sync(0xFFFFFFFFu, best, m));
                if (s == 0) atomicMin(&g_real_min[j], __float_as_uint(best));
            }
        // column direction: min over j per i (symmetry: dist(i,j)=dist(j,i))
#pragma unroll
        for (int nt = 0; nt < 4; nt++)
#pragma unroll
            for (int c = 0; c < 2; c++) {
                const int i = i0 + wn * 32 + nt * 8 + 2 * s + c;
                float best = __int_as_float(0x7f800000);
#pragma unroll
                for (int mt = 0; mt < 4; mt++)
#pragma unroll
                    for (int dl = 0; dl < 2; dl++)
                        best = fminf(best, d[mt][nt][dl * 2 + c]);
#pragma unroll
                for (int m = 4; m < 32; m <<= 1)
                    best = fminf(best, __shfl_xor_sync(0xFFFFFFFFu, best, m));
                if (g == 0) atomicMin(&g_real_min[i], __float_as_uint(best));
            }
    }
}

__global__ void final_kernel(float* __restrict__ out) {
    __shared__ float red[256];
    float sacc = 0.0f;
    for (int j = threadIdx.x; j < NREAL; j += 256) {
        unsigned long long p = g_gen_min[j];
        float d1 = sqrtf(__uint_as_float((unsigned)(p >> 32)));
        unsigned idx = (unsigned)(p & 0xFFFFFFFFu);
        float d2 = sqrtf(__uint_as_float(g_real_min[idx]));
        sacc += 1.0f / (1.0f + expf(-(d2 - d1) * 10.0f));
    }
    red[threadIdx.x] = sacc;
    __syncthreads();
    for (int o = 128; o > 0; o >>= 1) {
        if (threadIdx.x < o) red[threadIdx.x] += red[threadIdx.x + o];
        __syncthreads();
    }
    if (threadIdx.x == 0) out[0] = -100.0f * red[0] / (float)NREAL;
}

// ---------------- launcher ----------------
extern "C" void kernel_launch(void* const* d_in, const int* in_sizes, int n_in,
                              void* d_out, int out_size) {
    const float* real = (const float*)d_in[0];
    const float* gen  = (const float*)d_in[1];
    float* out = (float*)d_out;

    cudaFuncSetAttribute(dist_mma_kernel<false>,
                         cudaFuncAttributeMaxDynamicSharedMemorySize, SMEM_TOTAL);
    cudaFuncSetAttribute(dist_mma_kernel<true>,
                         cudaFuncAttributeMaxDynamicSharedMemorySize, SMEM_TOTAL);

    init_kernel<<<(NREAL + 255) / 256, 256>>>();
    norms_kernel<<<2 * NREAL, 256>>>(real, gen);

    dist_mma_kernel<false><<<NTRI, NTHR, SMEM_TOTAL>>>(real, real);
    dim3 grid2(NIB, NJB);   // 96 x 96
    dist_mma_kernel<true ><<<grid2, NTHR, SMEM_TOTAL>>>(gen, real);

    final_kernel<<<1, 256>>>(out);
}

// round 14
// speedup vs baseline: 4.9885x; 1.1832x over previous
#include <cuda_runtime.h>
#include <math.h>
#include <stdint.h>

#define NREAL 12288
#define DIM   256
#define BM    128          // j rows per CTA
#define BN    128          // i cols per CTA
#define BK    32           // K floats per stage
#define NSTG  (DIM / BK)   // 8
#define NTHR  256
#define NJB   (NREAL / BM)                   // 96
#define NIB   (NREAL / BN)                   // 96
#define NTRI  (NJB * (NJB + 1) / 2)          // 4656
#define A_BYTES     (BM * BK * 4)            // 16384
#define STAGE_BYTES ((BM + BN) * BK * 4)     // 32768
#define SMEM_TOTAL  (3 * STAGE_BYTES)        // 98304

__device__ float g_r2[NREAL];
__device__ float g_g2[NREAL];
__device__ unsigned int       g_real_min[NREAL];
__device__ unsigned long long g_gen_min[NREAL];

// tf32-rounded copies of the inputs (rounding done once, not per-LDS)
__device__ float g_realc[NREAL * DIM];
__device__ float g_genc [NREAL * DIM];

// ---------------- helpers ----------------
static __device__ __forceinline__ uint32_t smem_u32(const void* p) {
    uint32_t a;
    asm("{ .reg .u64 t; cvta.to.shared.u64 t, %1; cvt.u32.u64 %0, t; }"
        : "=r"(a) : "l"(p));
    return a;
}

static __device__ __forceinline__ void cp16(uint32_t dst, const void* src) {
    asm volatile("cp.async.cg.shared.global [%0], [%1], 16;" :: "r"(dst), "l"(src));
}
#define CP_COMMIT() asm volatile("cp.async.commit_group;" ::: "memory")

// raw bits (already tf32-rounded in the pre-pass)
static __device__ __forceinline__ uint32_t lds_u32(uint32_t a) {
    uint32_t v;
    asm("ld.shared.b32 %0, [%1];" : "=r"(v) : "r"(a));
    return v;
}

static __device__ __forceinline__ uint32_t to_tf32(float f) {
    uint32_t o;
    asm("cvt.rna.tf32.f32 %0, %1;" : "=r"(o) : "f"(f));
    return o;
}

static __device__ __forceinline__ void mma_tf32(
    float* d, const uint32_t* a, const uint32_t* b)
{
    asm volatile(
        "mma.sync.aligned.m16n8k8.row.col.f32.tf32.tf32.f32 "
        "{%0,%1,%2,%3}, {%4,%5,%6,%7}, {%8,%9}, {%0,%1,%2,%3};"
        : "+f"(d[0]), "+f"(d[1]), "+f"(d[2]), "+f"(d[3])
        : "r"(a[0]), "r"(a[1]), "r"(a[2]), "r"(a[3]), "r"(b[0]), "r"(b[1]));
}

// ---------------- small kernels ----------------
__global__ void init_kernel() {
    int j = blockIdx.x * blockDim.x + threadIdx.x;
    if (j < NREAL) {
        g_real_min[j] = 0x7F800000u;
        g_gen_min[j]  = 0x7F800000FFFFFFFFULL;
    }
}

// round-to-nearest tf32 pre-pass: real+gen -> g_realc/g_genc
__global__ void convert_kernel(const float* __restrict__ real,
                               const float* __restrict__ gen) {
    const int idx = blockIdx.x * blockDim.x + threadIdx.x;   // float4 index
    const int per = NREAL * DIM / 4;                          // per-tensor float4s
    const float4* src = (idx < per) ? (const float4*)real : (const float4*)gen;
    float4* dst = (idx < per) ? (float4*)g_realc : (float4*)g_genc;
    const int l = (idx < per) ? idx : idx - per;
    float4 v = src[l];
    uint4 o;
    o.x = to_tf32(v.x); o.y = to_tf32(v.y);
    o.z = to_tf32(v.z); o.w = to_tf32(v.w);
    ((uint4*)dst)[l] = o;
}

__global__ void norms_kernel(const float* __restrict__ real,
                             const float* __restrict__ gen) {
    __shared__ float red[256];
    int row = blockIdx.x;
    const float* src = (row < NREAL) ? real : gen;
    int r = (row < NREAL) ? row : row - NREAL;
    float v = src[(size_t)r * DIM + threadIdx.x];
    red[threadIdx.x] = v * v;
    __syncthreads();
    for (int o = 128; o > 0; o >>= 1) {
        if (threadIdx.x < o) red[threadIdx.x] += red[threadIdx.x + o];
        __syncthreads();
    }
    if (threadIdx.x == 0) {
        if (row < NREAL) g_r2[r] = red[0];
        else             g_g2[r] = red[0];
    }
}

// ---------------- fused tf32 mma.sync distance + mins ----------------
// m axis = j rows (gen rows for GEN, real rows for !GEN)
// n axis = i cols (real rows)
// GEN:  grid (NIB, NJB); min+argmin over i per j.
// !GEN: 1D grid over upper triangle (ib >= jb); symmetric — updates BOTH
//       row-mins (per j, over i) and col-mins (per i, over j).
template<bool GEN>
__global__ __launch_bounds__(NTHR, 2)
void dist_mma_kernel() {
    extern __shared__ __align__(1024) char dsm[];
    const uint32_t sbase = smem_u32(dsm);

    const float* __restrict__ Aj = GEN ? g_genc : g_realc;
    const float* __restrict__ Br = g_realc;

    int jb, ib;
    if (GEN) {
        jb = blockIdx.y; ib = blockIdx.x;
    } else {
        const int t = blockIdx.x;
        int p = (int)((193.0 - sqrt(193.0 * 193.0 - 8.0 * (double)t)) * 0.5);
        if (p < 0) p = 0;
        if (p > NJB - 1) p = NJB - 1;
        while (p + 1 <= NJB - 1 && ((p + 1) * NJB - ((p + 1) * p) / 2) <= t) p++;
        while (p > 0 && (p * NJB - (p * (p - 1)) / 2) > t) p--;
        jb = p;
        ib = jb + (t - (p * NJB - (p * (p - 1)) / 2));
    }
    const int j0 = jb * BM;
    const int i0 = ib * BN;

    const int tid  = threadIdx.x;
    const int w    = tid >> 5, lane = tid & 31;
    const int g    = lane >> 2, s = lane & 3;
    const int wm   = w >> 2;          // 0..1 (64 j-rows each)
    const int wn   = w & 3;           // 0..3 (32 i-cols each)

    float d[4][4][4];
#pragma unroll
    for (int mt = 0; mt < 4; mt++)
#pragma unroll
        for (int nt = 0; nt < 4; nt++)
#pragma unroll
            for (int q = 0; q < 4; q++) d[mt][nt][q] = 0.0f;

    uint32_t arow[4], brow[4];
#pragma unroll
    for (int mt = 0; mt < 4; mt++)
        arow[mt] = (uint32_t)((wm * 64 + mt * 16 + g) * 128);
#pragma unroll
    for (int nt = 0; nt < 4; nt++)
        brow[nt] = (uint32_t)((wn * 32 + nt * 8 + g) * 128);

    auto load_stage = [&](int st, int buf) {
        const int k0 = st * BK;
        const uint32_t ab = sbase + buf * STAGE_BYTES;
        const uint32_t bb = ab + A_BYTES;
#pragma unroll
        for (int t = 0; t < 4; t++) {
            const int l = tid + t * NTHR;      // 0..1023
            const int row = l >> 3, c = l & 7;
            cp16(ab + row * 128 + ((c ^ (row & 7)) << 4),
                 Aj + (size_t)(j0 + row) * DIM + k0 + c * 4);
        }
#pragma unroll
        for (int t = 0; t < 4; t++) {
            const int l = tid + t * NTHR;
            const int row = l >> 3, c = l & 7;
            cp16(bb + row * 128 + ((c ^ (row & 7)) << 4),
                 Br + (size_t)(i0 + row) * DIM + k0 + c * 4);
        }
        CP_COMMIT();
    };

    load_stage(0, 0);
    load_stage(1, 1);

    for (int st = 0; st < NSTG; st++) {
        if (st < NSTG - 1) asm volatile("cp.async.wait_group 1;" ::: "memory");
        else               asm volatile("cp.async.wait_group 0;" ::: "memory");
        __syncthreads();   // single barrier per stage: orders producers before
                           // consumers AND retires buffer (st-1)%3 == (st+2)%3
        if (st + 2 < NSTG) load_stage(st + 2, (st + 2) % 3);

        const uint32_t ab = sbase + (st % 3) * STAGE_BYTES;
        const uint32_t bb = ab + A_BYTES;
#pragma unroll
        for (int k8 = 0; k8 < 4; k8++) {
            const uint32_t t0 = ((uint32_t)((2 * k8) ^ g)) * 16 + s * 4;
            const uint32_t t1 = ((uint32_t)((2 * k8 + 1) ^ g)) * 16 + s * 4;
            uint32_t afr[4][4], bfr[4][2];
#pragma unroll
            for (int mt = 0; mt < 4; mt++) {
                afr[mt][0] = lds_u32(ab + arow[mt] + t0);
                afr[mt][1] = lds_u32(ab + arow[mt] + 8 * 128 + t0);
                afr[mt][2] = lds_u32(ab + arow[mt] + t1);
                afr[mt][3] = lds_u32(ab + arow[mt] + 8 * 128 + t1);
            }
#pragma unroll
            for (int nt = 0; nt < 4; nt++) {
                bfr[nt][0] = lds_u32(bb + brow[nt] + t0);
                bfr[nt][1] = lds_u32(bb + brow[nt] + t1);
            }
#pragma unroll
            for (int mt = 0; mt < 4; mt++)
#pragma unroll
                for (int nt = 0; nt < 4; nt++)
                    mma_tf32(d[mt][nt], afr[mt], bfr[nt]);
        }
    }

    // ------- epilogue: convert accumulators in place to squared distances -------
    float ri2[8];
#pragma unroll
    for (int nt = 0; nt < 4; nt++)
#pragma unroll
        for (int c = 0; c < 2; c++)
            ri2[nt * 2 + c] = g_r2[i0 + wn * 32 + nt * 8 + 2 * s + c];

    float rj2[8];
#pragma unroll
    for (int mt = 0; mt < 4; mt++)
#pragma unroll
        for (int dl = 0; dl < 2; dl++) {
            const int j = j0 + wm * 64 + mt * 16 + g + dl * 8;
            rj2[mt * 2 + dl] = GEN ? g_g2[j] : g_r2[j];
        }

#pragma unroll
    for (int mt = 0; mt < 4; mt++)
#pragma unroll
        for (int nt = 0; nt < 4; nt++)
#pragma unroll
            for (int dl = 0; dl < 2; dl++)
#pragma unroll
                for (int c = 0; c < 2; c++) {
                    float sq = fmaxf(ri2[nt * 2 + c] + rj2[mt * 2 + dl]
                                     - 2.0f * d[mt][nt][dl * 2 + c], 0.0f);
                    if (!GEN) {
                        const int i = i0 + wn * 32 + nt * 8 + 2 * s + c;
                        const int j = j0 + wm * 64 + mt * 16 + g + dl * 8;
                        if (i == j) sq = __int_as_float(0x7f800000);
                    }
                    d[mt][nt][dl * 2 + c] = sq;
                }

    if (GEN) {
        // min+argmin over i per j row; pack (sq_bits<<32)|i, lowest i on ties
#pragma unroll
        for (int mt = 0; mt < 4; mt++)
#pragma unroll
            for (int dl = 0; dl < 2; dl++) {
                const int j = j0 + wm * 64 + mt * 16 + g + dl * 8;
                unsigned long long best = 0x7F800000FFFFFFFFULL;
#pragma unroll
                for (int nt = 0; nt < 4; nt++)
#pragma unroll
                    for (int c = 0; c < 2; c++) {
                        const int i = i0 + wn * 32 + nt * 8 + 2 * s + c;
                        const unsigned long long pk =
                            ((unsigned long long)__float_as_uint(d[mt][nt][dl * 2 + c]) << 32)
                            | (unsigned)i;
                        if (pk < best) best = pk;
                    }
#pragma unroll
                for (int m = 1; m < 4; m <<= 1) {
                    unsigned long long o = __shfl_xor_sync(0xFFFFFFFFu, best, m);
                    if (o < best) best = o;
                }
                if (s == 0) atomicMin(&g_gen_min[j], best);
            }
    } else {
        // row direction: min over i per j
#pragma unroll
        for (int mt = 0; mt < 4; mt++)
#pragma unroll
            for (int dl = 0; dl < 2; dl++) {
                const int j = j0 + wm * 64 + mt * 16 + g + dl * 8;
                float best = __int_as_float(0x7f800000);
#pragma unroll
                for (int nt = 0; nt < 4; nt++)
#pragma unroll
                    for (int c = 0; c < 2; c++)
                        best = fminf(best, d[mt][nt][dl * 2 + c]);
#pragma unroll
                for (int m = 1; m < 4; m <<= 1)
                    best = fminf(best, __shfl_xor_sync(0xFFFFFFFFu, best, m));
                if (s == 0) atomicMin(&g_real_min[j], __float_as_uint(best));
            }
        // column direction: min over j per i (symmetry: dist(i,j)=dist(j,i))
#pragma unroll
        for (int nt = 0; nt < 4; nt++)
#pragma unroll
            for (int c = 0; c < 2; c++) {
                const int i = i0 + wn * 32 + nt * 8 + 2 * s + c;
                float best = __int_as_float(0x7f800000);
#pragma unroll
                for (int mt = 0; mt < 4; mt++)
#pragma unroll
                    for (int dl = 0; dl < 2; dl++)
                        best = fminf(best, d[mt][nt][dl * 2 + c]);
#pragma unroll
                for (int m = 4; m < 32; m <<= 1)
                    best = fminf(best, __shfl_xor_sync(0xFFFFFFFFu, best, m));
                if (g == 0) atomicMin(&g_real_min[i], __float_as_uint(best));
            }
    }
}

__global__ void final_kernel(float* __restrict__ out) {
    __shared__ float red[256];
    float sacc = 0.0f;
    for (int j = threadIdx.x; j < NREAL; j += 256) {
        unsigned long long p = g_gen_min[j];
        float d1 = sqrtf(__uint_as_float((unsigned)(p >> 32)));
        unsigned idx = (unsigned)(p & 0xFFFFFFFFu);
        float d2 = sqrtf(__uint_as_float(g_real_min[idx]));
        sacc += 1.0f / (1.0f + expf(-(d2 - d1) * 10.0f));
    }
    red[threadIdx.x] = sacc;
    __syncthreads();
    for (int o = 128; o > 0; o >>= 1) {
        if (threadIdx.x < o) red[threadIdx.x] += red[threadIdx.x + o];
        __syncthreads();
    }
    if (threadIdx.x == 0) out[0] = -100.0f * red[0] / (float)NREAL;
}

// ---------------- launcher ----------------
extern "C" void kernel_launch(void* const* d_in, const int* in_sizes, int n_in,
                              void* d_out, int out_size) {
    const float* real = (const float*)d_in[0];
    const float* gen  = (const float*)d_in[1];
    float* out = (float*)d_out;

    cudaFuncSetAttribute(dist_mma_kernel<false>,
                         cudaFuncAttributeMaxDynamicSharedMemorySize, SMEM_TOTAL);
    cudaFuncSetAttribute(dist_mma_kernel<true>,
                         cudaFuncAttributeMaxDynamicSharedMemorySize, SMEM_TOTAL);

    init_kernel<<<(NREAL + 255) / 256, 256>>>();
    convert_kernel<<<2 * NREAL * DIM / 4 / 256, 256>>>(real, gen);
    norms_kernel<<<2 * NREAL, 256>>>(real, gen);

    dist_mma_kernel<false><<<NTRI, NTHR, SMEM_TOTAL>>>();
    dim3 grid2(NIB, NJB);   // 96 x 96
    dist_mma_kernel<true ><<<grid2, NTHR, SMEM_TOTAL>>>();

    final_kernel<<<1, 256>>>(out);
}

// round 15
// speedup vs baseline: 5.4166x; 1.0858x over previous
#include <cuda_runtime.h>
#include <math.h>
#include <stdint.h>

#define NREAL 12288
#define DIM   256
#define BM    128          // j rows per CTA
#define BN    128          // i cols per CTA
#define BK    32           // K floats per stage
#define NSTG  (DIM / BK)   // 8
#define NTHR  256
#define NJB   (NREAL / BM)                   // 96
#define NIB   (NREAL / BN)                   // 96
#define NTRI  (NJB * (NJB + 1) / 2)          // 4656
#define A_BYTES     (BM * BK * 4)            // 16384
#define STAGE_BYTES ((BM + BN) * BK * 4)     // 32768
#define SMEM_TOTAL  (3 * STAGE_BYTES)        // 98304

__device__ float g_r2[NREAL];
__device__ float g_g2[NREAL];
__device__ unsigned int       g_real_min[NREAL];
__device__ unsigned long long g_gen_min[NREAL];

// tf32-rounded copies of the inputs (rounding done once, not per-LDS)
__device__ float g_realc[NREAL * DIM];
__device__ float g_genc [NREAL * DIM];

// ---------------- helpers ----------------
static __device__ __forceinline__ uint32_t smem_u32(const void* p) {
    uint32_t a;
    asm("{ .reg .u64 t; cvta.to.shared.u64 t, %1; cvt.u32.u64 %0, t; }"
        : "=r"(a) : "l"(p));
    return a;
}

static __device__ __forceinline__ void cp16(uint32_t dst, const void* src) {
    asm volatile("cp.async.cg.shared.global [%0], [%1], 16;" :: "r"(dst), "l"(src));
}
#define CP_COMMIT() asm volatile("cp.async.commit_group;" ::: "memory")

static __device__ __forceinline__ uint32_t to_tf32(float f) {
    uint32_t o;
    asm("cvt.rna.tf32.f32 %0, %1;" : "=r"(o) : "f"(f));
    return o;
}

// ldmatrix: 4x (8 rows x 16B) blocks -> exact m16k8 tf32 A fragment
static __device__ __forceinline__ void ldsm_x4(uint32_t* r, uint32_t addr) {
    asm volatile("ldmatrix.sync.aligned.m8n8.x4.shared.b16 {%0,%1,%2,%3}, [%4];"
        : "=r"(r[0]), "=r"(r[1]), "=r"(r[2]), "=r"(r[3]) : "r"(addr));
}
// 2x (8 rows x 16B) blocks -> exact n8k8 tf32 B fragment
static __device__ __forceinline__ void ldsm_x2(uint32_t* r, uint32_t addr) {
    asm volatile("ldmatrix.sync.aligned.m8n8.x2.shared.b16 {%0,%1}, [%2];"
        : "=r"(r[0]), "=r"(r[1]) : "r"(addr));
}

static __device__ __forceinline__ void mma_tf32(
    float* d, const uint32_t* a, const uint32_t* b)
{
    asm volatile(
        "mma.sync.aligned.m16n8k8.row.col.f32.tf32.tf32.f32 "
        "{%0,%1,%2,%3}, {%4,%5,%6,%7}, {%8,%9}, {%0,%1,%2,%3};"
        : "+f"(d[0]), "+f"(d[1]), "+f"(d[2]), "+f"(d[3])
        : "r"(a[0]), "r"(a[1]), "r"(a[2]), "r"(a[3]), "r"(b[0]), "r"(b[1]));
}

// ---------------- small kernels ----------------
__global__ void init_kernel() {
    int j = blockIdx.x * blockDim.x + threadIdx.x;
    if (j < NREAL) {
        g_real_min[j] = 0x7F800000u;
        g_gen_min[j]  = 0x7F800000FFFFFFFFULL;
    }
}

// round-to-nearest tf32 pre-pass: real+gen -> g_realc/g_genc
__global__ void convert_kernel(const float* __restrict__ real,
                               const float* __restrict__ gen) {
    const int idx = blockIdx.x * blockDim.x + threadIdx.x;   // float4 index
    const int per = NREAL * DIM / 4;
    const float4* src = (idx < per) ? (const float4*)real : (const float4*)gen;
    float4* dst = (idx < per) ? (float4*)g_realc : (float4*)g_genc;
    const int l = (idx < per) ? idx : idx - per;
    float4 v = src[l];
    uint4 o;
    o.x = to_tf32(v.x); o.y = to_tf32(v.y);
    o.z = to_tf32(v.z); o.w = to_tf32(v.w);
    ((uint4*)dst)[l] = o;
}

__global__ void norms_kernel(const float* __restrict__ real,
                             const float* __restrict__ gen) {
    __shared__ float red[256];
    int row = blockIdx.x;
    const float* src = (row < NREAL) ? real : gen;
    int r = (row < NREAL) ? row : row - NREAL;
    float v = src[(size_t)r * DIM + threadIdx.x];
    red[threadIdx.x] = v * v;
    __syncthreads();
    for (int o = 128; o > 0; o >>= 1) {
        if (threadIdx.x < o) red[threadIdx.x] += red[threadIdx.x + o];
        __syncthreads();
    }
    if (threadIdx.x == 0) {
        if (row < NREAL) g_r2[r] = red[0];
        else             g_g2[r] = red[0];
    }
}

// ---------------- fused tf32 mma.sync distance + mins ----------------
template<bool GEN>
__global__ __launch_bounds__(NTHR, 2)
void dist_mma_kernel() {
    extern __shared__ __align__(1024) char dsm[];
    const uint32_t sbase = smem_u32(dsm);

    const float* __restrict__ Aj = GEN ? g_genc : g_realc;
    const float* __restrict__ Br = g_realc;

    int jb, ib;
    if (GEN) {
        jb = blockIdx.y; ib = blockIdx.x;
    } else {
        const int t = blockIdx.x;
        int p = (int)((193.0 - sqrt(193.0 * 193.0 - 8.0 * (double)t)) * 0.5);
        if (p < 0) p = 0;
        if (p > NJB - 1) p = NJB - 1;
        while (p + 1 <= NJB - 1 && ((p + 1) * NJB - ((p + 1) * p) / 2) <= t) p++;
        while (p > 0 && (p * NJB - (p * (p - 1)) / 2) > t) p--;
        jb = p;
        ib = jb + (t - (p * NJB - (p * (p - 1)) / 2));
    }
    const int j0 = jb * BM;
    const int i0 = ib * BN;

    const int tid  = threadIdx.x;
    const int w    = tid >> 5, lane = tid & 31;
    const int g    = lane >> 2, s = lane & 3;
    const int wm   = w >> 2;          // 0..1 (64 j-rows each)
    const int wn   = w & 3;           // 0..3 (32 i-cols each)
    const uint32_t l7 = (uint32_t)(lane & 7);

    float d[4][4][4];
#pragma unroll
    for (int mt = 0; mt < 4; mt++)
#pragma unroll
        for (int nt = 0; nt < 4; nt++)
#pragma unroll
            for (int q = 0; q < 4; q++) d[mt][nt][q] = 0.0f;

    // per-lane ldmatrix row base offsets (bytes, within stage A / B regions)
    uint32_t arowoff[4], browoff[4];
#pragma unroll
    for (int mt = 0; mt < 4; mt++)
        arowoff[mt] = (uint32_t)((wm * 64 + mt * 16 + ((lane >> 3) & 1) * 8 + (lane & 7)) * 128);
#pragma unroll
    for (int nt = 0; nt < 4; nt++)
        browoff[nt] = (uint32_t)((wn * 32 + nt * 8 + (lane & 7)) * 128);
    const uint32_t selA = (uint32_t)(lane >> 4);         // 0/1: k0-3 vs k4-7 block pair
    const uint32_t selB = (uint32_t)((lane >> 3) & 1);

    auto load_stage = [&](int st, int buf) {
        const int k0 = st * BK;
        const uint32_t ab = sbase + buf * STAGE_BYTES;
        const uint32_t bb = ab + A_BYTES;
#pragma unroll
        for (int t = 0; t < 4; t++) {
            const int l = tid + t * NTHR;      // 0..1023
            const int row = l >> 3, c = l & 7;
            cp16(ab + row * 128 + ((c ^ (row & 7)) << 4),
                 Aj + (size_t)(j0 + row) * DIM + k0 + c * 4);
        }
#pragma unroll
        for (int t = 0; t < 4; t++) {
            const int l = tid + t * NTHR;
            const int row = l >> 3, c = l & 7;
            cp16(bb + row * 128 + ((c ^ (row & 7)) << 4),
                 Br + (size_t)(i0 + row) * DIM + k0 + c * 4);
        }
        CP_COMMIT();
    };

    load_stage(0, 0);
    load_stage(1, 1);

    for (int st = 0; st < NSTG; st++) {
        if (st < NSTG - 1) asm volatile("cp.async.wait_group 1;" ::: "memory");
        else               asm volatile("cp.async.wait_group 0;" ::: "memory");
        __syncthreads();   // single barrier: orders producers before consumers
                           // and retires buffer (st-1)%3 == (st+2)%3
        if (st + 2 < NSTG) load_stage(st + 2, (st + 2) % 3);

        const uint32_t ab = sbase + (st % 3) * STAGE_BYTES;
        const uint32_t bb = ab + A_BYTES;
#pragma unroll
        for (int k8 = 0; k8 < 4; k8++) {
            // swizzled 16B-column selector for this k8 (per-lane)
            const uint32_t colA = (((uint32_t)(2 * k8) + selA) ^ l7) << 4;
            const uint32_t colB = (((uint32_t)(2 * k8) + selB) ^ l7) << 4;
            uint32_t afr[4][4], bfr[4][2];
#pragma unroll
            for (int mt = 0; mt < 4; mt++)
                ldsm_x4(afr[mt], ab + arowoff[mt] + colA);
#pragma unroll
            for (int nt = 0; nt < 4; nt++)
                ldsm_x2(bfr[nt], bb + browoff[nt] + colB);
#pragma unroll
            for (int mt = 0; mt < 4; mt++)
#pragma unroll
                for (int nt = 0; nt < 4; nt++)
                    mma_tf32(d[mt][nt], afr[mt], bfr[nt]);
        }
    }

    // ------- epilogue: convert accumulators in place to squared distances -------
    float ri2[8];
#pragma unroll
    for (int nt = 0; nt < 4; nt++)
#pragma unroll
        for (int c = 0; c < 2; c++)
            ri2[nt * 2 + c] = g_r2[i0 + wn * 32 + nt * 8 + 2 * s + c];

    float rj2[8];
#pragma unroll
    for (int mt = 0; mt < 4; mt++)
#pragma unroll
        for (int dl = 0; dl < 2; dl++) {
            const int j = j0 + wm * 64 + mt * 16 + g + dl * 8;
            rj2[mt * 2 + dl] = GEN ? g_g2[j] : g_r2[j];
        }

#pragma unroll
    for (int mt = 0; mt < 4; mt++)
#pragma unroll
        for (int nt = 0; nt < 4; nt++)
#pragma unroll
            for (int dl = 0; dl < 2; dl++)
#pragma unroll
                for (int c = 0; c < 2; c++) {
                    float sq = fmaxf(ri2[nt * 2 + c] + rj2[mt * 2 + dl]
                                     - 2.0f * d[mt][nt][dl * 2 + c], 0.0f);
                    if (!GEN) {
                        const int i = i0 + wn * 32 + nt * 8 + 2 * s + c;
                        const int j = j0 + wm * 64 + mt * 16 + g + dl * 8;
                        if (i == j) sq = __int_as_float(0x7f800000);
                    }
                    d[mt][nt][dl * 2 + c] = sq;
                }

    if (GEN) {
        // min+argmin over i per j row; pack (sq_bits<<32)|i, lowest i on ties
#pragma unroll
        for (int mt = 0; mt < 4; mt++)
#pragma unroll
            for (int dl = 0; dl < 2; dl++) {
                const int j = j0 + wm * 64 + mt * 16 + g + dl * 8;
                unsigned long long best = 0x7F800000FFFFFFFFULL;
#pragma unroll
                for (int nt = 0; nt < 4; nt++)
#pragma unroll
                    for (int c = 0; c < 2; c++) {
                        const int i = i0 + wn * 32 + nt * 8 + 2 * s + c;
                        const unsigned long long pk =
                            ((unsigned long long)__float_as_uint(d[mt][nt][dl * 2 + c]) << 32)
                            | (unsigned)i;
                        if (pk < best) best = pk;
                    }
#pragma unroll
                for (int m = 1; m < 4; m <<= 1) {
                    unsigned long long o = __shfl_xor_sync(0xFFFFFFFFu, best, m);
                    if (o < best) best = o;
                }
                if (s == 0) atomicMin(&g_gen_min[j], best);
            }
    } else {
        // row direction: min over i per j
#pragma unroll
        for (int mt = 0; mt < 4; mt++)
#pragma unroll
            for (int dl = 0; dl < 2; dl++) {
                const int j = j0 + wm * 64 + mt * 16 + g + dl * 8;
                float best = __int_as_float(0x7f800000);
#pragma unroll
                for (int nt = 0; nt < 4; nt++)
#pragma unroll
                    for (int c = 0; c < 2; c++)
                        best = fminf(best, d[mt][nt][dl * 2 + c]);
#pragma unroll
                for (int m = 1; m < 4; m <<= 1)
                    best = fminf(best, __shfl_xor_sync(0xFFFFFFFFu, best, m));
                if (s == 0) atomicMin(&g_real_min[j], __float_as_uint(best));
            }
        // column direction: min over j per i (symmetry: dist(i,j)=dist(j,i))
#pragma unroll
        for (int nt = 0; nt < 4; nt++)
#pragma unroll
            for (int c = 0; c < 2; c++) {
                const int i = i0 + wn * 32 + nt * 8 + 2 * s + c;
                float best = __int_as_float(0x7f800000);
#pragma unroll
                for (int mt = 0; mt < 4; mt++)
#pragma unroll
                    for (int dl = 0; dl < 2; dl++)
                        best = fminf(best, d[mt][nt][dl * 2 + c]);
#pragma unroll
                for (int m = 4; m < 32; m <<= 1)
                    best = fminf(best, __shfl_xor_sync(0xFFFFFFFFu, best, m));
                if (g == 0) atomicMin(&g_real_min[i], __float_as_uint(best));
            }
    }
}

__global__ void final_kernel(float* __restrict__ out) {
    __shared__ float red[256];
    float sacc = 0.0f;
    for (int j = threadIdx.x; j < NREAL; j += 256) {
        unsigned long long p = g_gen_min[j];
        float d1 = sqrtf(__uint_as_float((unsigned)(p >> 32)));
        unsigned idx = (unsigned)(p & 0xFFFFFFFFu);
        float d2 = sqrtf(__uint_as_float(g_real_min[idx]));
        sacc += 1.0f / (1.0f + expf(-(d2 - d1) * 10.0f));
    }
    red[threadIdx.x] = sacc;
    __syncthreads();
    for (int o = 128; o > 0; o >>= 1) {
        if (threadIdx.x < o) red[threadIdx.x] += red[threadIdx.x + o];
        __syncthreads();
    }
    if (threadIdx.x == 0) out[0] = -100.0f * red[0] / (float)NREAL;
}

// ---------------- launcher ----------------
extern "C" void kernel_launch(void* const* d_in, const int* in_sizes, int n_in,
                              void* d_out, int out_size) {
    const float* real = (const float*)d_in[0];
    const float* gen  = (const float*)d_in[1];
    float* out = (float*)d_out;

    cudaFuncSetAttribute(dist_mma_kernel<false>,
                         cudaFuncAttributeMaxDynamicSharedMemorySize, SMEM_TOTAL);
    cudaFuncSetAttribute(dist_mma_kernel<true>,
                         cudaFuncAttributeMaxDynamicSharedMemorySize, SMEM_TOTAL);

    init_kernel<<<(NREAL + 255) / 256, 256>>>();
    convert_kernel<<<2 * NREAL * DIM / 4 / 256, 256>>>(real, gen);
    norms_kernel<<<2 * NREAL, 256>>>(real, gen);

    dist_mma_kernel<false><<<NTRI, NTHR, SMEM_TOTAL>>>();
    dim3 grid2(NIB, NJB);   // 96 x 96
    dist_mma_kernel<true ><<<grid2, NTHR, SMEM_TOTAL>>>();

    final_kernel<<<1, 256>>>(out);
}

// round 16
// speedup vs baseline: 9.5933x; 1.7711x over previous
#include <cuda_runtime.h>
#include <cuda_fp16.h>
#include <math.h>
#include <stdint.h>

#define NREAL 12288
#define DIM   256
#define BM    128          // j rows per CTA
#define BN    128          // i cols per CTA
#define BK    64           // K halves per stage (= 128B row)
#define NSTG  (DIM / BK)   // 4
#define NTHR  256
#define NJB   (NREAL / BM)                   // 96
#define NIB   (NREAL / BN)                   // 96
#define NTRI  (NJB * (NJB + 1) / 2)          // 4656
#define A_BYTES     (BM * BK * 2)            // 16384
#define STAGE_BYTES ((BM + BN) * BK * 2)     // 32768
#define SMEM_TOTAL  (3 * STAGE_BYTES)        // 98304

__device__ float g_r2[NREAL];
__device__ float g_g2[NREAL];
__device__ unsigned int       g_real_min[NREAL];
__device__ unsigned long long g_gen_min[NREAL];

// fp16 copies of the inputs (round-to-nearest, done once)
__device__ __half g_realh[NREAL * DIM];
__device__ __half g_genh [NREAL * DIM];

// ---------------- helpers ----------------
static __device__ __forceinline__ uint32_t smem_u32(const void* p) {
    uint32_t a;
    asm("{ .reg .u64 t; cvta.to.shared.u64 t, %1; cvt.u32.u64 %0, t; }"
        : "=r"(a) : "l"(p));
    return a;
}

static __device__ __forceinline__ void cp16(uint32_t dst, const void* src) {
    asm volatile("cp.async.cg.shared.global [%0], [%1], 16;" :: "r"(dst), "l"(src));
}
#define CP_COMMIT() asm volatile("cp.async.commit_group;" ::: "memory")

// ldmatrix: 4x (8 rows x 16B) blocks -> m16k16 fp16 A fragment
static __device__ __forceinline__ void ldsm_x4(uint32_t* r, uint32_t addr) {
    asm volatile("ldmatrix.sync.aligned.m8n8.x4.shared.b16 {%0,%1,%2,%3}, [%4];"
        : "=r"(r[0]), "=r"(r[1]), "=r"(r[2]), "=r"(r[3]) : "r"(addr));
}
// 2x (8 rows x 16B) blocks -> n8k16 fp16 B fragment
static __device__ __forceinline__ void ldsm_x2(uint32_t* r, uint32_t addr) {
    asm volatile("ldmatrix.sync.aligned.m8n8.x2.shared.b16 {%0,%1}, [%2];"
        : "=r"(r[0]), "=r"(r[1]) : "r"(addr));
}

static __device__ __forceinline__ void mma_f16(
    float* d, const uint32_t* a, const uint32_t* b)
{
    asm volatile(
        "mma.sync.aligned.m16n8k16.row.col.f32.f16.f16.f32 "
        "{%0,%1,%2,%3}, {%4,%5,%6,%7}, {%8,%9}, {%0,%1,%2,%3};"
        : "+f"(d[0]), "+f"(d[1]), "+f"(d[2]), "+f"(d[3])
        : "r"(a[0]), "r"(a[1]), "r"(a[2]), "r"(a[3]), "r"(b[0]), "r"(b[1]));
}

// ---------------- small kernels ----------------
__global__ void init_kernel() {
    int j = blockIdx.x * blockDim.x + threadIdx.x;
    if (j < NREAL) {
        g_real_min[j] = 0x7F800000u;
        g_gen_min[j]  = 0x7F800000FFFFFFFFULL;
    }
}

// fp32 -> fp16 (rn) pre-pass: real+gen -> g_realh/g_genh
__global__ void convert_kernel(const float* __restrict__ real,
                               const float* __restrict__ gen) {
    const int idx = blockIdx.x * blockDim.x + threadIdx.x;   // float4 index
    const int per = NREAL * DIM / 4;
    const float4* src = (idx < per) ? (const float4*)real : (const float4*)gen;
    __half* dst = (idx < per) ? g_realh : g_genh;
    const int l = (idx < per) ? idx : idx - per;
    float4 v = src[l];
    __half2 h0 = __floats2half2_rn(v.x, v.y);
    __half2 h1 = __floats2half2_rn(v.z, v.w);
    ((uint2*)dst)[l] = make_uint2(*(uint32_t*)&h0, *(uint32_t*)&h1);
}

__global__ void norms_kernel(const float* __restrict__ real,
                             const float* __restrict__ gen) {
    __shared__ float red[256];
    int row = blockIdx.x;
    const float* src = (row < NREAL) ? real : gen;
    int r = (row < NREAL) ? row : row - NREAL;
    float v = src[(size_t)r * DIM + threadIdx.x];
    red[threadIdx.x] = v * v;
    __syncthreads();
    for (int o = 128; o > 0; o >>= 1) {
        if (threadIdx.x < o) red[threadIdx.x] += red[threadIdx.x + o];
        __syncthreads();
    }
    if (threadIdx.x == 0) {
        if (row < NREAL) g_r2[r] = red[0];
        else             g_g2[r] = red[0];
    }
}

// ---------------- fused fp16 mma.sync distance + mins ----------------
// m axis = j rows (gen for GEN, real for !GEN); n axis = i cols (real rows)
template<bool GEN>
__global__ __launch_bounds__(NTHR, 2)
void dist_mma_kernel() {
    extern __shared__ __align__(1024) char dsm[];
    const uint32_t sbase = smem_u32(dsm);

    const __half* __restrict__ Aj = GEN ? g_genh : g_realh;
    const __half* __restrict__ Br = g_realh;

    int jb, ib;
    if (GEN) {
        jb = blockIdx.y; ib = blockIdx.x;
    } else {
        const int t = blockIdx.x;
        int p = (int)((193.0 - sqrt(193.0 * 193.0 - 8.0 * (double)t)) * 0.5);
        if (p < 0) p = 0;
        if (p > NJB - 1) p = NJB - 1;
        while (p + 1 <= NJB - 1 && ((p + 1) * NJB - ((p + 1) * p) / 2) <= t) p++;
        while (p > 0 && (p * NJB - (p * (p - 1)) / 2) > t) p--;
        jb = p;
        ib = jb + (t - (p * NJB - (p * (p - 1)) / 2));
    }
    const int j0 = jb * BM;
    const int i0 = ib * BN;

    const int tid  = threadIdx.x;
    const int w    = tid >> 5, lane = tid & 31;
    const int g    = lane >> 2, s = lane & 3;
    const int wm   = w >> 2;          // 0..1 (64 j-rows each)
    const int wn   = w & 3;           // 0..3 (32 i-cols each)
    const uint32_t l7 = (uint32_t)(lane & 7);

    float d[4][4][4];
#pragma unroll
    for (int mt = 0; mt < 4; mt++)
#pragma unroll
        for (int nt = 0; nt < 4; nt++)
#pragma unroll
            for (int q = 0; q < 4; q++) d[mt][nt][q] = 0.0f;

    // per-lane ldmatrix row base offsets (bytes, within stage A / B regions)
    uint32_t arowoff[4], browoff[4];
#pragma unroll
    for (int mt = 0; mt < 4; mt++)
        arowoff[mt] = (uint32_t)((wm * 64 + mt * 16 + ((lane >> 3) & 1) * 8 + (lane & 7)) * 128);
#pragma unroll
    for (int nt = 0; nt < 4; nt++)
        browoff[nt] = (uint32_t)((wn * 32 + nt * 8 + (lane & 7)) * 128);
    const uint32_t selA = (uint32_t)(lane >> 4);         // x4: chunk-pair select
    const uint32_t selB = (uint32_t)((lane >> 3) & 1);   // x2: chunk select

    auto load_stage = [&](int st, int buf) {
        const int k0 = st * BK;                           // in halves
        const uint32_t ab = sbase + buf * STAGE_BYTES;
        const uint32_t bb = ab + A_BYTES;
#pragma unroll
        for (int t = 0; t < 4; t++) {
            const int l = tid + t * NTHR;      // 0..1023
            const int row = l >> 3, c = l & 7;
            cp16(ab + row * 128 + ((c ^ (row & 7)) << 4),
                 Aj + (size_t)(j0 + row) * DIM + k0 + c * 8);
        }
#pragma unroll
        for (int t = 0; t < 4; t++) {
            const int l = tid + t * NTHR;
            const int row = l >> 3, c = l & 7;
            cp16(bb + row * 128 + ((c ^ (row & 7)) << 4),
                 Br + (size_t)(i0 + row) * DIM + k0 + c * 8);
        }
        CP_COMMIT();
    };

    load_stage(0, 0);
    load_stage(1, 1);

    for (int st = 0; st < NSTG; st++) {
        if (st < NSTG - 1) asm volatile("cp.async.wait_group 1;" ::: "memory");
        else               asm volatile("cp.async.wait_group 0;" ::: "memory");
        __syncthreads();   // orders producers before consumers; retires the
                           // buffer about to be refilled below
        if (st + 2 < NSTG) load_stage(st + 2, (st + 2) % 3);

        const uint32_t ab = sbase + (st % 3) * STAGE_BYTES;
        const uint32_t bb = ab + A_BYTES;
#pragma unroll
        for (int kk = 0; kk < 4; kk++) {       // 4 x k16 per K=64 stage
            const uint32_t colA = (((uint32_t)(2 * kk) + selA) ^ l7) << 4;
            const uint32_t colB = (((uint32_t)(2 * kk) + selB) ^ l7) << 4;
            uint32_t afr[4][4], bfr[4][2];
#pragma unroll
            for (int mt = 0; mt < 4; mt++)
                ldsm_x4(afr[mt], ab + arowoff[mt] + colA);
#pragma unroll
            for (int nt = 0; nt < 4; nt++)
                ldsm_x2(bfr[nt], bb + browoff[nt] + colB);
#pragma unroll
            for (int mt = 0; mt < 4; mt++)
#pragma unroll
                for (int nt = 0; nt < 4; nt++)
                    mma_f16(d[mt][nt], afr[mt], bfr[nt]);
        }
    }

    // ------- epilogue: convert accumulators in place to squared distances -------
    float ri2[8];
#pragma unroll
    for (int nt = 0; nt < 4; nt++)
#pragma unroll
        for (int c = 0; c < 2; c++)
            ri2[nt * 2 + c] = g_r2[i0 + wn * 32 + nt * 8 + 2 * s + c];

    float rj2[8];
#pragma unroll
    for (int mt = 0; mt < 4; mt++)
#pragma unroll
        for (int dl = 0; dl < 2; dl++) {
            const int j = j0 + wm * 64 + mt * 16 + g + dl * 8;
            rj2[mt * 2 + dl] = GEN ? g_g2[j] : g_r2[j];
        }

#pragma unroll
    for (int mt = 0; mt < 4; mt++)
#pragma unroll
        for (int nt = 0; nt < 4; nt++)
#pragma unroll
            for (int dl = 0; dl < 2; dl++)
#pragma unroll
                for (int c = 0; c < 2; c++) {
                    float sq = fmaxf(ri2[nt * 2 + c] + rj2[mt * 2 + dl]
                                     - 2.0f * d[mt][nt][dl * 2 + c], 0.0f);
                    if (!GEN) {
                        const int i = i0 + wn * 32 + nt * 8 + 2 * s + c;
                        const int j = j0 + wm * 64 + mt * 16 + g + dl * 8;
                        if (i == j) sq = __int_as_float(0x7f800000);
                    }
                    d[mt][nt][dl * 2 + c] = sq;
                }

    if (GEN) {
        // min+argmin over i per j row; pack (sq_bits<<32)|i, lowest i on ties
#pragma unroll
        for (int mt = 0; mt < 4; mt++)
#pragma unroll
            for (int dl = 0; dl < 2; dl++) {
                const int j = j0 + wm * 64 + mt * 16 + g + dl * 8;
                unsigned long long best = 0x7F800000FFFFFFFFULL;
#pragma unroll
                for (int nt = 0; nt < 4; nt++)
#pragma unroll
                    for (int c = 0; c < 2; c++) {
                        const int i = i0 + wn * 32 + nt * 8 + 2 * s + c;
                        const unsigned long long pk =
                            ((unsigned long long)__float_as_uint(d[mt][nt][dl * 2 + c]) << 32)
                            | (unsigned)i;
                        if (pk < best) best = pk;
                    }
#pragma unroll
                for (int m = 1; m < 4; m <<= 1) {
                    unsigned long long o = __shfl_xor_sync(0xFFFFFFFFu, best, m);
                    if (o < best) best = o;
                }
                if (s == 0) atomicMin(&g_gen_min[j], best);
            }
    } else {
        // row direction: min over i per j
#pragma unroll
        for (int mt = 0; mt < 4; mt++)
#pragma unroll
            for (int dl = 0; dl < 2; dl++) {
                const int j = j0 + wm * 64 + mt * 16 + g + dl * 8;
                float best = __int_as_float(0x7f800000);
#pragma unroll
                for (int nt = 0; nt < 4; nt++)
#pragma unroll
                    for (int c = 0; c < 2; c++)
                        best = fminf(best, d[mt][nt][dl * 2 + c]);
#pragma unroll
                for (int m = 1; m < 4; m <<= 1)
                    best = fminf(best, __shfl_xor_sync(0xFFFFFFFFu, best, m));
                if (s == 0) atomicMin(&g_real_min[j], __float_as_uint(best));
            }
        // column direction: min over j per i (symmetry)
#pragma unroll
        for (int nt = 0; nt < 4; nt++)
#pragma unroll
            for (int c = 0; c < 2; c++) {
                const int i = i0 + wn * 32 + nt * 8 + 2 * s + c;
                float best = __int_as_float(0x7f800000);
#pragma unroll
                for (int mt = 0; mt < 4; mt++)
#pragma unroll
                    for (int dl = 0; dl < 2; dl++)
                        best = fminf(best, d[mt][nt][dl * 2 + c]);
#pragma unroll
                for (int m = 4; m < 32; m <<= 1)
                    best = fminf(best, __shfl_xor_sync(0xFFFFFFFFu, best, m));
                if (g == 0) atomicMin(&g_real_min[i], __float_as_uint(best));
            }
    }
}

__global__ void final_kernel(float* __restrict__ out) {
    __shared__ float red[256];
    float sacc = 0.0f;
    for (int j = threadIdx.x; j < NREAL; j += 256) {
        unsigned long long p = g_gen_min[j];
        float d1 = sqrtf(__uint_as_float((unsigned)(p >> 32)));
        unsigned idx = (unsigned)(p & 0xFFFFFFFFu);
        float d2 = sqrtf(__uint_as_float(g_real_min[idx]));
        sacc += 1.0f / (1.0f + expf(-(d2 - d1) * 10.0f));
    }
    red[threadIdx.x] = sacc;
    __syncthreads();
    for (int o = 128; o > 0; o >>= 1) {
        if (threadIdx.x < o) red[threadIdx.x] += red[threadIdx.x + o];
        __syncthreads();
    }
    if (threadIdx.x == 0) out[0] = -100.0f * red[0] / (float)NREAL;
}

// ---------------- launcher ----------------
extern "C" void kernel_launch(void* const* d_in, const int* in_sizes, int n_in,
                              void* d_out, int out_size) {
    const float* real = (const float*)d_in[0];
    const float* gen  = (const float*)d_in[1];
    float* out = (float*)d_out;

    cudaFuncSetAttribute(dist_mma_kernel<false>,
                         cudaFuncAttributeMaxDynamicSharedMemorySize, SMEM_TOTAL);
    cudaFuncSetAttribute(dist_mma_kernel<true>,
                         cudaFuncAttributeMaxDynamicSharedMemorySize, SMEM_TOTAL);

    init_kernel<<<(NREAL + 255) / 256, 256>>>();
    convert_kernel<<<2 * NREAL * DIM / 4 / 256, 256>>>(real, gen);
    norms_kernel<<<2 * NREAL, 256>>>(real, gen);

    dist_mma_kernel<false><<<NTRI, NTHR, SMEM_TOTAL>>>();
    dim3 grid2(NIB, NJB);   // 96 x 96
    dist_mma_kernel<true ><<<grid2, NTHR, SMEM_TOTAL>>>();

    final_kernel<<<1, 256>>>(out);
}